// round 15
// baseline (speedup 1.0000x reference)
#include <cuda_runtime.h>
#include <cuda_fp16.h>
#include <cstdint>
#include <cstddef>

#define BB 32
#define NN 2048
#define DD 128
#define HH 128

// Scratch (allocation-free rule: static device arrays).
// g_q/g_k: fp16x2 h-pair-packed uint32 [B*N][64].
// g_v:     fp16x2 j-pair-packed uint32 [B*1024][128].
// g_mb:    bit-packed mask, word = 32 j of one row: [B*N][64] u32.
__device__ float g_q[BB * NN * HH];
__device__ float g_k[BB * NN * HH];
__device__ float g_v[BB * NN * HH];
__device__ uint32_t g_mb[BB * NN * 64];

// pack two fp32 -> fp16x2 (lo = a, hi = b), saturating to finite
__device__ __forceinline__ uint32_t h2pack(float a, float b) {
    uint32_t r;
    asm("cvt.rn.satfinite.f16x2.f32 %0, %1, %2;" : "=r"(r) : "f"(b), "f"(a));
    return r;
}
__device__ __forceinline__ float tanha(float x) {
    float r;
    asm("tanh.approx.f32 %0, %1;" : "=f"(r) : "f"(x));
    return r;
}

// warp mma: D(16x8) += A(16x16,row,f16) * B(16x8,col,f16), fp32 accum
__device__ __forceinline__ void mma16n8k16h(float* c, const uint32_t* a,
                                            uint32_t b0, uint32_t b1) {
    asm volatile(
        "mma.sync.aligned.m16n8k16.row.col.f32.f16.f16.f32 "
        "{%0,%1,%2,%3}, {%4,%5,%6,%7}, {%8,%9}, {%0,%1,%2,%3};"
        : "+f"(c[0]), "+f"(c[1]), "+f"(c[2]), "+f"(c[3])
        : "r"(a[0]), "r"(a[1]), "r"(a[2]), "r"(a[3]), "r"(b0), "r"(b1));
}

__device__ __forceinline__ uint32_t smem_u32(const void* p) {
    uint32_t a;
    asm("{ .reg .u64 t; cvta.to.shared.u64 t, %1; cvt.u32.u64 %0, t; }"
        : "=r"(a) : "l"(p));
    return a;
}

#define CP_ASYNC16(dst, src)                                                \
    asm volatile("cp.async.cg.shared.global [%0], [%1], 16;" ::             \
                     "r"(dst), "l"(src) : "memory")
#define CP_COMMIT() asm volatile("cp.async.commit_group;" ::: "memory")
#define CP_WAIT0() asm volatile("cp.async.wait_group 0;" ::: "memory")
#define CP_WAIT1() asm volatile("cp.async.wait_group 1;" ::: "memory")

// ============================================================
// Kernel A: QKV projection via fp16 MMA with hi/lo error split,
// PLUS (blockIdx.y == 3) warp-ballot bit-packing of the mask.
//   y = tanh(x @ W + b);  y ~= xh@Wh + xh@Wl + xl@Wh  (fp32-faithful)
// Outputs: q/k fp16x2 h-pair packed [row][64]; v fp16x2 j-pair packed;
//          g_mb bit mask (exact: mask is 0.0/1.0).
// smem (u32 words): Xh[128][68] | Xl[128][68] | Wh[128][68] | Wl[128][68]
// ============================================================
#define PW 68
#define PX_H 0
#define PX_L 8704
#define PW_H 17408
#define PW_L 26112
#define SMEM_PROJ (34816 * 4)

__global__ __launch_bounds__(256, 1) void proj_kernel(
    const float* __restrict__ x, const float* __restrict__ mask,
    const float* __restrict__ Wq, const float* __restrict__ bq,
    const float* __restrict__ Wk, const float* __restrict__ bk,
    const float* __restrict__ Wv, const float* __restrict__ bv) {
    extern __shared__ uint32_t ps[];
    const int tid = threadIdx.x;
    const int lane = tid & 31;
    const int w = tid >> 5;
    const int qp = lane >> 2;
    const int ql = lane & 3;
    const int row0 = blockIdx.x * 128;

    if (blockIdx.y == 3) {
        // ---- mask bit-pack: warp ballot, 1024 words per warp ----
        const uint32_t gw = blockIdx.x * 8 + w;      // 0..4095
        const uint32_t wbase = gw * 1024;            // word index base
#pragma unroll 4
        for (int it = 0; it < 1024; it++) {
            const uint32_t widx = wbase + it;
            float mval = __ldg(mask + (size_t)widx * 32 + lane);
            uint32_t bits = __ballot_sync(0xffffffffu, mval != 0.0f);
            if (lane == 0) g_mb[widx] = bits;
        }
        return;
    }

    const float* W;
    const float* bias;
    float* outp;
    bool isV = false;
    if (blockIdx.y == 0)      { W = Wq; bias = bq; outp = g_q; }
    else if (blockIdx.y == 1) { W = Wk; bias = bk; outp = g_k; }
    else                      { W = Wv; bias = bv; outp = g_v; isV = true; }

    // ---- load + split x tile (128 x 128 f32) ----
#pragma unroll
    for (int t = 0; t < 16; t++) {
        const int idx = tid + t * 256;
        const int row = idx >> 5, c = idx & 31;
        float4 v = *reinterpret_cast<const float4*>(
            x + (size_t)(row0 + row) * DD + 4 * c);
        float rx = __half2float(__float2half_rn(v.x));
        float ry = __half2float(__float2half_rn(v.y));
        float rz = __half2float(__float2half_rn(v.z));
        float rw = __half2float(__float2half_rn(v.w));
        uint2 uh, ul;
        uh.x = h2pack(v.x, v.y);
        uh.y = h2pack(v.z, v.w);
        ul.x = h2pack(v.x - rx, v.y - ry);
        ul.y = h2pack(v.z - rz, v.w - rw);
        *reinterpret_cast<uint2*>(ps + PX_H + row * PW + 2 * c) = uh;
        *reinterpret_cast<uint2*>(ps + PX_L + row * PW + 2 * c) = ul;
    }
    // ---- load + split W transposed: Wt[n][kp] = (W[2kp][n], W[2kp+1][n]) ----
#pragma unroll
    for (int t = 0; t < 32; t++) {
        const int idx = tid + t * 256;
        const int kp = idx >> 7, n = idx & 127;
        float a = __ldg(W + (size_t)(2 * kp) * HH + n);
        float b = __ldg(W + (size_t)(2 * kp + 1) * HH + n);
        float ra = __half2float(__float2half_rn(a));
        float rb = __half2float(__float2half_rn(b));
        ps[PW_H + n * PW + kp] = h2pack(a, b);
        ps[PW_L + n * PW + kp] = h2pack(a - ra, b - rb);
    }
    __syncthreads();

    // ---- 3-pass MMA: Xh*Wh + Xh*Wl + Xl*Wh ----
    float oacc[16][4];
#pragma unroll
    for (int nb = 0; nb < 16; nb++)
#pragma unroll
        for (int c = 0; c < 4; c++) oacc[nb][c] = 0.0f;

    const int r0 = w * 16 + qp;
    const uint32_t* a0h = ps + PX_H + r0 * PW + ql;
    const uint32_t* a0l = ps + PX_L + r0 * PW + ql;

#pragma unroll 1
    for (int pass = 0; pass < 3; pass++) {
        const uint32_t* A0 = (pass == 2) ? a0l : a0h;
        const uint32_t* A1 = A0 + 8 * PW;
        const uint32_t* Wb = ps + ((pass == 1) ? PW_L : PW_H);
#pragma unroll
        for (int kk = 0; kk < 8; kk++) {
            uint32_t qa[4];
            qa[0] = A0[kk * 8];
            qa[1] = A1[kk * 8];
            qa[2] = A0[kk * 8 + 4];
            qa[3] = A1[kk * 8 + 4];
#pragma unroll
            for (int nb = 0; nb < 16; nb++) {
                const uint32_t* kb = Wb + (nb * 8 + qp) * PW + kk * 8 + ql;
                mma16n8k16h(oacc[nb], qa, kb[0], kb[4]);
            }
        }
    }

    // ---- epilogue: bias + tanh.approx + pack + store ----
#pragma unroll
    for (int nb = 0; nb < 16; nb++) {
        const int n0 = nb * 8 + 2 * ql;
        float2 bb = __ldg(reinterpret_cast<const float2*>(bias + n0));
        float t0 = tanha(oacc[nb][0] + bb.x);
        float t1 = tanha(oacc[nb][1] + bb.y);
        float t2 = tanha(oacc[nb][2] + bb.x);
        float t3 = tanha(oacc[nb][3] + bb.y);
        if (!isV) {
            uint32_t* o2 = reinterpret_cast<uint32_t*>(outp);
            o2[(size_t)(row0 + r0) * 64 + nb * 4 + ql] = h2pack(t0, t1);
            o2[(size_t)(row0 + r0 + 8) * 64 + nb * 4 + ql] = h2pack(t2, t3);
        } else {
            float s0 = __shfl_xor_sync(0xffffffffu, t0, 4);
            float s1 = __shfl_xor_sync(0xffffffffu, t1, 4);
            float s2 = __shfl_xor_sync(0xffffffffu, t2, 4);
            float s3 = __shfl_xor_sync(0xffffffffu, t3, 4);
            uint32_t* v2 = reinterpret_cast<uint32_t*>(g_v);
            if (!(qp & 1)) {
                const size_t jp = (size_t)(row0 + w * 16 + qp) >> 1;
                uint2 u;
                u.x = h2pack(t0, s0);
                u.y = h2pack(t1, s1);
                *reinterpret_cast<uint2*>(v2 + jp * HH + nb * 8 + 2 * ql) = u;
            } else {
                const size_t jp = (size_t)(row0 + w * 16 + 8 + qp - 1) >> 1;
                uint2 u;
                u.x = h2pack(s2, t2);
                u.y = h2pack(s3, t3);
                *reinterpret_cast<uint2*>(v2 + jp * HH + nb * 8 + 2 * ql) = u;
            }
        }
    }
}

// ============================================================
// Kernel B: flash attention v13.
//  - 64-j stages (32 stages), triple-buffered K/V, ONE sync/stage
//  - Q fragments persistent in registers; BIT mask (one u64 LDG per
//    row-pair per stage) -> no mask cp.async, no mask smem
//  - stage processed in two 32-j halves (sf[4] keeps regs ~128)
// smem (words): Kh 3x[64][68] | Vt 3x[32][136]  = 102 KB
// ============================================================
#define QLDH 68
#define KSTRIDE (64 * QLDH)
#define VT_OFF (3 * KSTRIDE)
#define VSTRIDE (32 * 136)
#define SMEM_ATT ((VT_OFF + 3 * VSTRIDE) * 4)

__device__ __forceinline__ void attn_stage_copy(uint32_t smb, int s,
                                                const uint32_t* kg2,
                                                const uint32_t* vg2, int tid) {
    const int buf = s % 3;
    const uint32_t kdst = smb + (uint32_t)(buf * KSTRIDE) * 4;
    const uint32_t vdst = smb + (uint32_t)(VT_OFF + buf * VSTRIDE) * 4;
    const uint32_t* kn = kg2 + (size_t)(s * 64) * 64;
    const uint32_t* vn = vg2 + (size_t)(s * 32) * HH;
#pragma unroll
    for (int t = 0; t < 4; t++) {
        const int idx = tid + t * 256;       // 0..1023
        const int krow = idx >> 4, kc = idx & 15;
        CP_ASYNC16(kdst + (uint32_t)(krow * QLDH + kc * 4) * 4,
                   kn + (size_t)krow * 64 + kc * 4);
        const int vrow = idx >> 5, vc = idx & 31;
        CP_ASYNC16(vdst + (uint32_t)(vrow * 136 + vc * 4) * 4,
                   vn + (size_t)vrow * HH + vc * 4);
    }
}

__global__ __launch_bounds__(256, 2) void attn_mma(float* __restrict__ out) {
    extern __shared__ uint32_t smw[];
    const uint32_t smb = smem_u32(smw);

    const int tid = threadIdx.x;
    const int lane = tid & 31;
    const int w = tid >> 5;
    const int b = blockIdx.x >> 4;
    const int i0 = (blockIdx.x & 15) << 7;
    const int qp = lane >> 2;
    const int ql = lane & 3;
    const int r0 = w * 16 + qp;

    const uint32_t* qg2 =
        reinterpret_cast<const uint32_t*>(g_q) + ((size_t)(b * NN) + i0) * 64;
    const uint32_t* kg2 =
        reinterpret_cast<const uint32_t*>(g_k) + (size_t)(b * NN) * 64;
    const uint32_t* vg2 =
        reinterpret_cast<const uint32_t*>(g_v) + (size_t)b * 1024 * HH;
    const uint32_t* mb0 = g_mb + ((size_t)(b * NN) + i0 + r0) * 64;
    const uint32_t* mb1 = mb0 + (size_t)8 * 64;

    // ---- prologue: stage0, stage1 copies in flight ----
    attn_stage_copy(smb, 0, kg2, vg2, tid);
    CP_COMMIT();
    attn_stage_copy(smb, 1, kg2, vg2, tid);
    CP_COMMIT();

    // ---- persistent Q fragments in registers (fp16-packed) ----
    uint32_t qa_all[8][4];
    {
        const uint32_t* q0 = qg2 + (size_t)r0 * 64 + ql;
        const uint32_t* q1 = qg2 + (size_t)(r0 + 8) * 64 + ql;
#pragma unroll
        for (int kk = 0; kk < 8; kk++) {
            qa_all[kk][0] = __ldg(q0 + kk * 8);
            qa_all[kk][1] = __ldg(q1 + kk * 8);
            qa_all[kk][2] = __ldg(q0 + kk * 8 + 4);
            qa_all[kk][3] = __ldg(q1 + kk * 8 + 4);
        }
    }

    float oa[16][4];
#pragma unroll
    for (int h = 0; h < 16; h++)
#pragma unroll
        for (int c = 0; c < 4; c++) oa[h][c] = 0.0f;
    float ls0 = 0.0f, ls1 = 0.0f;

#pragma unroll 1
    for (int jt = 0; jt < 32; jt++) {
        if (jt < 31) { CP_WAIT1(); } else { CP_WAIT0(); }
        __syncthreads();   // stage jt resident; all warps done with jt-1

        if (jt < 30) {
            attn_stage_copy(smb, jt + 2, kg2, vg2, tid);
            CP_COMMIT();
        }

        const uint32_t* Kh = smw + (jt % 3) * KSTRIDE;
        const uint32_t* sVt = smw + VT_OFF + (jt % 3) * VSTRIDE;

        // ---- bit mask for this 64-j stage: one u64 per row ----
        const unsigned long long mw0 = __ldg(
            reinterpret_cast<const unsigned long long*>(mb0 + 2 * jt));
        const unsigned long long mw1 = __ldg(
            reinterpret_cast<const unsigned long long*>(mb1 + 2 * jt));

#pragma unroll
        for (int hf = 0; hf < 2; hf++) {
            const uint32_t w0 = (uint32_t)(mw0 >> (hf * 32));
            const uint32_t w1 = (uint32_t)(mw1 >> (hf * 32));

            // ---- S = Q K^T over this half's 32 j ----
            float sf[4][4];
#pragma unroll
            for (int nb = 0; nb < 4; nb++)
#pragma unroll
                for (int c = 0; c < 4; c++) sf[nb][c] = 0.0f;

#pragma unroll
            for (int kk = 0; kk < 8; kk++) {
#pragma unroll
                for (int nb = 0; nb < 4; nb++) {
                    const uint32_t* kb =
                        Kh + (hf * 32 + nb * 8 + qp) * QLDH + kk * 8 + ql;
                    mma16n8k16h(sf[nb], qa_all[kk], kb[0], kb[4]);
                }
            }

            // ---- per nb-pair: bit test + exp(s-10) + fp16 pack + PV ----
#pragma unroll
            for (int m = 0; m < 2; m++) {
                const int nE = 2 * m, nO = 2 * m + 1;
                const int bE = nE * 8 + 2 * ql;
                const int bO = nO * 8 + 2 * ql;
                float pE0 = ((w0 >> bE) & 1u) ? __expf(sf[nE][0] - 10.0f) : 0.0f;
                float pE1 = ((w0 >> (bE + 1)) & 1u) ? __expf(sf[nE][1] - 10.0f) : 0.0f;
                float pE2 = ((w1 >> bE) & 1u) ? __expf(sf[nE][2] - 10.0f) : 0.0f;
                float pE3 = ((w1 >> (bE + 1)) & 1u) ? __expf(sf[nE][3] - 10.0f) : 0.0f;
                float pO0 = ((w0 >> bO) & 1u) ? __expf(sf[nO][0] - 10.0f) : 0.0f;
                float pO1 = ((w0 >> (bO + 1)) & 1u) ? __expf(sf[nO][1] - 10.0f) : 0.0f;
                float pO2 = ((w1 >> bO) & 1u) ? __expf(sf[nO][2] - 10.0f) : 0.0f;
                float pO3 = ((w1 >> (bO + 1)) & 1u) ? __expf(sf[nO][3] - 10.0f) : 0.0f;
                ls0 += (pE0 + pE1) + (pO0 + pO1);
                ls1 += (pE2 + pE3) + (pO2 + pO3);
                uint32_t pa[4];
                pa[0] = h2pack(pE0, pE1);
                pa[1] = h2pack(pE2, pE3);
                pa[2] = h2pack(pO0, pO1);
                pa[3] = h2pack(pO2, pO3);

                const uint32_t* vb0 = sVt + (hf * 16 + m * 8 + ql) * 136 + qp;
                const uint32_t* vb1 = vb0 + 4 * 136;
#pragma unroll
                for (int h = 0; h < 16; h++) {
                    mma16n8k16h(oa[h], pa, vb0[h * 8], vb1[h * 8]);
                }
            }
        }
    }

    // ---- epilogue: quad reduction, normalize, store ----
    ls0 += __shfl_xor_sync(0xffffffffu, ls0, 1);
    ls0 += __shfl_xor_sync(0xffffffffu, ls0, 2);
    ls1 += __shfl_xor_sync(0xffffffffu, ls1, 1);
    ls1 += __shfl_xor_sync(0xffffffffu, ls1, 2);
    const float inv0 = 1.0f / ls0;
    const float inv1 = 1.0f / ls1;
    float* orow0 = out + ((size_t)(b * NN) + i0 + r0) * HH + 2 * ql;
    float* orow1 = orow0 + (size_t)8 * HH;
#pragma unroll
    for (int h = 0; h < 16; h++) {
        float2 v0, v1;
        v0.x = oa[h][0] * inv0; v0.y = oa[h][1] * inv0;
        v1.x = oa[h][2] * inv1; v1.y = oa[h][3] * inv1;
        *reinterpret_cast<float2*>(orow0 + h * 8) = v0;
        *reinterpret_cast<float2*>(orow1 + h * 8) = v1;
    }
}

extern "C" void kernel_launch(void* const* d_in, const int* in_sizes, int n_in,
                              void* d_out, int out_size) {
    const float* x    = (const float*)d_in[0];
    const float* mask = (const float*)d_in[1];
    const float* Wv   = (const float*)d_in[2];
    const float* bv   = (const float*)d_in[3];
    const float* Wk   = (const float*)d_in[4];
    const float* bk   = (const float*)d_in[5];
    const float* Wq   = (const float*)d_in[6];
    const float* bq   = (const float*)d_in[7];
    float* out = (float*)d_out;

    cudaFuncSetAttribute(proj_kernel, cudaFuncAttributeMaxDynamicSharedMemorySize,
                         SMEM_PROJ);
    cudaFuncSetAttribute(attn_mma, cudaFuncAttributeMaxDynamicSharedMemorySize,
                         SMEM_ATT);

    proj_kernel<<<dim3(512, 4, 1), 256, SMEM_PROJ>>>(x, mask, Wq, bq, Wk, bk,
                                                     Wv, bv);
    attn_mma<<<512, 256, SMEM_ATT>>>(out);
}

// round 16
// speedup vs baseline: 1.5930x; 1.5930x over previous
#include <cuda_runtime.h>
#include <cuda_fp16.h>
#include <cstdint>
#include <cstddef>

#define BB 32
#define NN 2048
#define DD 128
#define HH 128

// Scratch (allocation-free rule: static device arrays).
// g_q/g_k: fp16x2 h-pair-packed uint32 [B*N][64].
// g_v:     fp16x2 j-pair-packed uint32 [B*1024][128].
// g_mb:    bit-packed mask, word = 32 j of one row: [B*N][64] u32.
__device__ float g_q[BB * NN * HH];
__device__ float g_k[BB * NN * HH];
__device__ float g_v[BB * NN * HH];
__device__ uint32_t g_mb[BB * NN * 64];

// pack two fp32 -> fp16x2 (lo = a, hi = b), saturating to finite
__device__ __forceinline__ uint32_t h2pack(float a, float b) {
    uint32_t r;
    asm("cvt.rn.satfinite.f16x2.f32 %0, %1, %2;" : "=r"(r) : "f"(b), "f"(a));
    return r;
}
__device__ __forceinline__ float tanha(float x) {
    float r;
    asm("tanh.approx.f32 %0, %1;" : "=f"(r) : "f"(x));
    return r;
}

// warp mma: D(16x8) += A(16x16,row,f16) * B(16x8,col,f16), fp32 accum
__device__ __forceinline__ void mma16n8k16h(float* c, const uint32_t* a,
                                            uint32_t b0, uint32_t b1) {
    asm volatile(
        "mma.sync.aligned.m16n8k16.row.col.f32.f16.f16.f32 "
        "{%0,%1,%2,%3}, {%4,%5,%6,%7}, {%8,%9}, {%0,%1,%2,%3};"
        : "+f"(c[0]), "+f"(c[1]), "+f"(c[2]), "+f"(c[3])
        : "r"(a[0]), "r"(a[1]), "r"(a[2]), "r"(a[3]), "r"(b0), "r"(b1));
}

__device__ __forceinline__ uint32_t smem_u32(const void* p) {
    uint32_t a;
    asm("{ .reg .u64 t; cvta.to.shared.u64 t, %1; cvt.u32.u64 %0, t; }"
        : "=r"(a) : "l"(p));
    return a;
}

#define CP_ASYNC16(dst, src)                                                \
    asm volatile("cp.async.cg.shared.global [%0], [%1], 16;" ::             \
                     "r"(dst), "l"(src) : "memory")
#define CP_COMMIT() asm volatile("cp.async.commit_group;" ::: "memory")
#define CP_WAIT0() asm volatile("cp.async.wait_group 0;" ::: "memory")
#define CP_WAIT1() asm volatile("cp.async.wait_group 1;" ::: "memory")

// ============================================================
// Kernel A: QKV projection via fp16 MMA with hi/lo error split,
// PLUS (blockIdx.y == 3) warp-ballot bit-packing of the mask with
// 16-DEEP MLP BATCHING (16 independent coalesced LDGs per iteration;
// MLP=1 serial ballot loop was the R15 regression).
//   y = tanh(x @ W + b);  y ~= xh@Wh + xh@Wl + xl@Wh  (fp32-faithful)
// smem (u32 words): Xh[128][68] | Xl[128][68] | Wh[128][68] | Wl[128][68]
// ============================================================
#define PW 68
#define PX_H 0
#define PX_L 8704
#define PW_H 17408
#define PW_L 26112
#define SMEM_PROJ (34816 * 4)

__global__ __launch_bounds__(256, 1) void proj_kernel(
    const float* __restrict__ x, const float* __restrict__ mask,
    const float* __restrict__ Wq, const float* __restrict__ bq,
    const float* __restrict__ Wk, const float* __restrict__ bk,
    const float* __restrict__ Wv, const float* __restrict__ bv) {
    extern __shared__ uint32_t ps[];
    const int tid = threadIdx.x;
    const int lane = tid & 31;
    const int w = tid >> 5;
    const int qp = lane >> 2;
    const int ql = lane & 3;
    const int row0 = blockIdx.x * 128;

    if (blockIdx.y == 3) {
        // ---- mask bit-pack: 16-word batches for MLP ----
        const uint32_t gw = blockIdx.x * 8 + w;      // 0..4095
        const uint32_t wbase = gw * 1024;            // word index base
#pragma unroll 1
        for (int it = 0; it < 64; it++) {
            const uint32_t base = wbase + it * 16;
            float mv[16];
#pragma unroll
            for (int u = 0; u < 16; u++)
                mv[u] = __ldg(mask + (size_t)(base + u) * 32 + lane);
            uint32_t bits[16];
#pragma unroll
            for (int u = 0; u < 16; u++)
                bits[u] = __ballot_sync(0xffffffffu, mv[u] != 0.0f);
            if (lane == 0) {
#pragma unroll
                for (int u = 0; u < 16; u += 4) {
                    uint4 uu;
                    uu.x = bits[u];
                    uu.y = bits[u + 1];
                    uu.z = bits[u + 2];
                    uu.w = bits[u + 3];
                    *reinterpret_cast<uint4*>(g_mb + base + u) = uu;
                }
            }
        }
        return;
    }

    const float* W;
    const float* bias;
    float* outp;
    bool isV = false;
    if (blockIdx.y == 0)      { W = Wq; bias = bq; outp = g_q; }
    else if (blockIdx.y == 1) { W = Wk; bias = bk; outp = g_k; }
    else                      { W = Wv; bias = bv; outp = g_v; isV = true; }

    // ---- load + split x tile (128 x 128 f32) ----
#pragma unroll
    for (int t = 0; t < 16; t++) {
        const int idx = tid + t * 256;
        const int row = idx >> 5, c = idx & 31;
        float4 v = *reinterpret_cast<const float4*>(
            x + (size_t)(row0 + row) * DD + 4 * c);
        float rx = __half2float(__float2half_rn(v.x));
        float ry = __half2float(__float2half_rn(v.y));
        float rz = __half2float(__float2half_rn(v.z));
        float rw = __half2float(__float2half_rn(v.w));
        uint2 uh, ul;
        uh.x = h2pack(v.x, v.y);
        uh.y = h2pack(v.z, v.w);
        ul.x = h2pack(v.x - rx, v.y - ry);
        ul.y = h2pack(v.z - rz, v.w - rw);
        *reinterpret_cast<uint2*>(ps + PX_H + row * PW + 2 * c) = uh;
        *reinterpret_cast<uint2*>(ps + PX_L + row * PW + 2 * c) = ul;
    }
    // ---- load + split W transposed: Wt[n][kp] = (W[2kp][n], W[2kp+1][n]) ----
#pragma unroll
    for (int t = 0; t < 32; t++) {
        const int idx = tid + t * 256;
        const int kp = idx >> 7, n = idx & 127;
        float a = __ldg(W + (size_t)(2 * kp) * HH + n);
        float b = __ldg(W + (size_t)(2 * kp + 1) * HH + n);
        float ra = __half2float(__float2half_rn(a));
        float rb = __half2float(__float2half_rn(b));
        ps[PW_H + n * PW + kp] = h2pack(a, b);
        ps[PW_L + n * PW + kp] = h2pack(a - ra, b - rb);
    }
    __syncthreads();

    // ---- 3-pass MMA: Xh*Wh + Xh*Wl + Xl*Wh ----
    float oacc[16][4];
#pragma unroll
    for (int nb = 0; nb < 16; nb++)
#pragma unroll
        for (int c = 0; c < 4; c++) oacc[nb][c] = 0.0f;

    const int r0 = w * 16 + qp;
    const uint32_t* a0h = ps + PX_H + r0 * PW + ql;
    const uint32_t* a0l = ps + PX_L + r0 * PW + ql;

#pragma unroll 1
    for (int pass = 0; pass < 3; pass++) {
        const uint32_t* A0 = (pass == 2) ? a0l : a0h;
        const uint32_t* A1 = A0 + 8 * PW;
        const uint32_t* Wb = ps + ((pass == 1) ? PW_L : PW_H);
#pragma unroll
        for (int kk = 0; kk < 8; kk++) {
            uint32_t qa[4];
            qa[0] = A0[kk * 8];
            qa[1] = A1[kk * 8];
            qa[2] = A0[kk * 8 + 4];
            qa[3] = A1[kk * 8 + 4];
#pragma unroll
            for (int nb = 0; nb < 16; nb++) {
                const uint32_t* kb = Wb + (nb * 8 + qp) * PW + kk * 8 + ql;
                mma16n8k16h(oacc[nb], qa, kb[0], kb[4]);
            }
        }
    }

    // ---- epilogue: bias + tanh.approx + pack + store ----
#pragma unroll
    for (int nb = 0; nb < 16; nb++) {
        const int n0 = nb * 8 + 2 * ql;
        float2 bb = __ldg(reinterpret_cast<const float2*>(bias + n0));
        float t0 = tanha(oacc[nb][0] + bb.x);
        float t1 = tanha(oacc[nb][1] + bb.y);
        float t2 = tanha(oacc[nb][2] + bb.x);
        float t3 = tanha(oacc[nb][3] + bb.y);
        if (!isV) {
            uint32_t* o2 = reinterpret_cast<uint32_t*>(outp);
            o2[(size_t)(row0 + r0) * 64 + nb * 4 + ql] = h2pack(t0, t1);
            o2[(size_t)(row0 + r0 + 8) * 64 + nb * 4 + ql] = h2pack(t2, t3);
        } else {
            float s0 = __shfl_xor_sync(0xffffffffu, t0, 4);
            float s1 = __shfl_xor_sync(0xffffffffu, t1, 4);
            float s2 = __shfl_xor_sync(0xffffffffu, t2, 4);
            float s3 = __shfl_xor_sync(0xffffffffu, t3, 4);
            uint32_t* v2 = reinterpret_cast<uint32_t*>(g_v);
            if (!(qp & 1)) {
                const size_t jp = (size_t)(row0 + w * 16 + qp) >> 1;
                uint2 u;
                u.x = h2pack(t0, s0);
                u.y = h2pack(t1, s1);
                *reinterpret_cast<uint2*>(v2 + jp * HH + nb * 8 + 2 * ql) = u;
            } else {
                const size_t jp = (size_t)(row0 + w * 16 + 8 + qp - 1) >> 1;
                uint2 u;
                u.x = h2pack(s2, t2);
                u.y = h2pack(s3, t3);
                *reinterpret_cast<uint2*>(v2 + jp * HH + nb * 8 + 2 * ql) = u;
            }
        }
    }
}

// ============================================================
// Kernel B: flash attention v13 (unchanged from R15 — 298us).
//  - 64-j stages (32 stages), triple-buffered K/V, ONE sync/stage
//  - Q fragments persistent in registers; BIT mask (one u64 LDG per
//    row-pair per stage) -> no mask cp.async, no mask smem
// smem (words): Kh 3x[64][68] | Vt 3x[32][136]  = 102 KB
// ============================================================
#define QLDH 68
#define KSTRIDE (64 * QLDH)
#define VT_OFF (3 * KSTRIDE)
#define VSTRIDE (32 * 136)
#define SMEM_ATT ((VT_OFF + 3 * VSTRIDE) * 4)

__device__ __forceinline__ void attn_stage_copy(uint32_t smb, int s,
                                                const uint32_t* kg2,
                                                const uint32_t* vg2, int tid) {
    const int buf = s % 3;
    const uint32_t kdst = smb + (uint32_t)(buf * KSTRIDE) * 4;
    const uint32_t vdst = smb + (uint32_t)(VT_OFF + buf * VSTRIDE) * 4;
    const uint32_t* kn = kg2 + (size_t)(s * 64) * 64;
    const uint32_t* vn = vg2 + (size_t)(s * 32) * HH;
#pragma unroll
    for (int t = 0; t < 4; t++) {
        const int idx = tid + t * 256;       // 0..1023
        const int krow = idx >> 4, kc = idx & 15;
        CP_ASYNC16(kdst + (uint32_t)(krow * QLDH + kc * 4) * 4,
                   kn + (size_t)krow * 64 + kc * 4);
        const int vrow = idx >> 5, vc = idx & 31;
        CP_ASYNC16(vdst + (uint32_t)(vrow * 136 + vc * 4) * 4,
                   vn + (size_t)vrow * HH + vc * 4);
    }
}

__global__ __launch_bounds__(256, 2) void attn_mma(float* __restrict__ out) {
    extern __shared__ uint32_t smw[];
    const uint32_t smb = smem_u32(smw);

    const int tid = threadIdx.x;
    const int lane = tid & 31;
    const int w = tid >> 5;
    const int b = blockIdx.x >> 4;
    const int i0 = (blockIdx.x & 15) << 7;
    const int qp = lane >> 2;
    const int ql = lane & 3;
    const int r0 = w * 16 + qp;

    const uint32_t* qg2 =
        reinterpret_cast<const uint32_t*>(g_q) + ((size_t)(b * NN) + i0) * 64;
    const uint32_t* kg2 =
        reinterpret_cast<const uint32_t*>(g_k) + (size_t)(b * NN) * 64;
    const uint32_t* vg2 =
        reinterpret_cast<const uint32_t*>(g_v) + (size_t)b * 1024 * HH;
    const uint32_t* mb0 = g_mb + ((size_t)(b * NN) + i0 + r0) * 64;
    const uint32_t* mb1 = mb0 + (size_t)8 * 64;

    // ---- prologue: stage0, stage1 copies in flight ----
    attn_stage_copy(smb, 0, kg2, vg2, tid);
    CP_COMMIT();
    attn_stage_copy(smb, 1, kg2, vg2, tid);
    CP_COMMIT();

    // ---- persistent Q fragments in registers (fp16-packed) ----
    uint32_t qa_all[8][4];
    {
        const uint32_t* q0 = qg2 + (size_t)r0 * 64 + ql;
        const uint32_t* q1 = qg2 + (size_t)(r0 + 8) * 64 + ql;
#pragma unroll
        for (int kk = 0; kk < 8; kk++) {
            qa_all[kk][0] = __ldg(q0 + kk * 8);
            qa_all[kk][1] = __ldg(q1 + kk * 8);
            qa_all[kk][2] = __ldg(q0 + kk * 8 + 4);
            qa_all[kk][3] = __ldg(q1 + kk * 8 + 4);
        }
    }

    float oa[16][4];
#pragma unroll
    for (int h = 0; h < 16; h++)
#pragma unroll
        for (int c = 0; c < 4; c++) oa[h][c] = 0.0f;
    float ls0 = 0.0f, ls1 = 0.0f;

#pragma unroll 1
    for (int jt = 0; jt < 32; jt++) {
        if (jt < 31) { CP_WAIT1(); } else { CP_WAIT0(); }
        __syncthreads();   // stage jt resident; all warps done with jt-1

        if (jt < 30) {
            attn_stage_copy(smb, jt + 2, kg2, vg2, tid);
            CP_COMMIT();
        }

        const uint32_t* Kh = smw + (jt % 3) * KSTRIDE;
        const uint32_t* sVt = smw + VT_OFF + (jt % 3) * VSTRIDE;

        // ---- bit mask for this 64-j stage: one u64 per row ----
        const unsigned long long mw0 = __ldg(
            reinterpret_cast<const unsigned long long*>(mb0 + 2 * jt));
        const unsigned long long mw1 = __ldg(
            reinterpret_cast<const unsigned long long*>(mb1 + 2 * jt));

#pragma unroll
        for (int hf = 0; hf < 2; hf++) {
            const uint32_t w0 = (uint32_t)(mw0 >> (hf * 32));
            const uint32_t w1 = (uint32_t)(mw1 >> (hf * 32));

            // ---- S = Q K^T over this half's 32 j ----
            float sf[4][4];
#pragma unroll
            for (int nb = 0; nb < 4; nb++)
#pragma unroll
                for (int c = 0; c < 4; c++) sf[nb][c] = 0.0f;

#pragma unroll
            for (int kk = 0; kk < 8; kk++) {
#pragma unroll
                for (int nb = 0; nb < 4; nb++) {
                    const uint32_t* kb =
                        Kh + (hf * 32 + nb * 8 + qp) * QLDH + kk * 8 + ql;
                    mma16n8k16h(sf[nb], qa_all[kk], kb[0], kb[4]);
                }
            }

            // ---- per nb-pair: bit test + exp(s-10) + fp16 pack + PV ----
#pragma unroll
            for (int m = 0; m < 2; m++) {
                const int nE = 2 * m, nO = 2 * m + 1;
                const int bE = nE * 8 + 2 * ql;
                const int bO = nO * 8 + 2 * ql;
                float pE0 = ((w0 >> bE) & 1u) ? __expf(sf[nE][0] - 10.0f) : 0.0f;
                float pE1 = ((w0 >> (bE + 1)) & 1u) ? __expf(sf[nE][1] - 10.0f) : 0.0f;
                float pE2 = ((w1 >> bE) & 1u) ? __expf(sf[nE][2] - 10.0f) : 0.0f;
                float pE3 = ((w1 >> (bE + 1)) & 1u) ? __expf(sf[nE][3] - 10.0f) : 0.0f;
                float pO0 = ((w0 >> bO) & 1u) ? __expf(sf[nO][0] - 10.0f) : 0.0f;
                float pO1 = ((w0 >> (bO + 1)) & 1u) ? __expf(sf[nO][1] - 10.0f) : 0.0f;
                float pO2 = ((w1 >> bO) & 1u) ? __expf(sf[nO][2] - 10.0f) : 0.0f;
                float pO3 = ((w1 >> (bO + 1)) & 1u) ? __expf(sf[nO][3] - 10.0f) : 0.0f;
                ls0 += (pE0 + pE1) + (pO0 + pO1);
                ls1 += (pE2 + pE3) + (pO2 + pO3);
                uint32_t pa[4];
                pa[0] = h2pack(pE0, pE1);
                pa[1] = h2pack(pE2, pE3);
                pa[2] = h2pack(pO0, pO1);
                pa[3] = h2pack(pO2, pO3);

                const uint32_t* vb0 = sVt + (hf * 16 + m * 8 + ql) * 136 + qp;
                const uint32_t* vb1 = vb0 + 4 * 136;
#pragma unroll
                for (int h = 0; h < 16; h++) {
                    mma16n8k16h(oa[h], pa, vb0[h * 8], vb1[h * 8]);
                }
            }
        }
    }

    // ---- epilogue: quad reduction, normalize, store ----
    ls0 += __shfl_xor_sync(0xffffffffu, ls0, 1);
    ls0 += __shfl_xor_sync(0xffffffffu, ls0, 2);
    ls1 += __shfl_xor_sync(0xffffffffu, ls1, 1);
    ls1 += __shfl_xor_sync(0xffffffffu, ls1, 2);
    const float inv0 = 1.0f / ls0;
    const float inv1 = 1.0f / ls1;
    float* orow0 = out + ((size_t)(b * NN) + i0 + r0) * HH + 2 * ql;
    float* orow1 = orow0 + (size_t)8 * HH;
#pragma unroll
    for (int h = 0; h < 16; h++) {
        float2 v0, v1;
        v0.x = oa[h][0] * inv0; v0.y = oa[h][1] * inv0;
        v1.x = oa[h][2] * inv1; v1.y = oa[h][3] * inv1;
        *reinterpret_cast<float2*>(orow0 + h * 8) = v0;
        *reinterpret_cast<float2*>(orow1 + h * 8) = v1;
    }
}

extern "C" void kernel_launch(void* const* d_in, const int* in_sizes, int n_in,
                              void* d_out, int out_size) {
    const float* x    = (const float*)d_in[0];
    const float* mask = (const float*)d_in[1];
    const float* Wv   = (const float*)d_in[2];
    const float* bv   = (const float*)d_in[3];
    const float* Wk   = (const float*)d_in[4];
    const float* bk   = (const float*)d_in[5];
    const float* Wq   = (const float*)d_in[6];
    const float* bq   = (const float*)d_in[7];
    float* out = (float*)d_out;

    cudaFuncSetAttribute(proj_kernel, cudaFuncAttributeMaxDynamicSharedMemorySize,
                         SMEM_PROJ);
    cudaFuncSetAttribute(attn_mma, cudaFuncAttributeMaxDynamicSharedMemorySize,
                         SMEM_ATT);

    proj_kernel<<<dim3(512, 4, 1), 256, SMEM_PROJ>>>(x, mask, Wq, bq, Wk, bk,
                                                     Wv, bv);
    attn_mma<<<512, 256, SMEM_ATT>>>(out);
}

// round 17
// speedup vs baseline: 1.6963x; 1.0648x over previous
#include <cuda_runtime.h>
#include <cuda_fp16.h>
#include <cstdint>
#include <cstddef>

#define BB 32
#define NN 2048
#define DD 128
#define HH 128

// Scratch (allocation-free rule: static device arrays).
// g_q/g_k: fp16x2 h-pair-packed uint32 [B*N][64].
// g_v:     fp16x2 j-pair-packed uint32 [B*1024][128].
// g_mb:    bit-packed mask, word = 32 j of one row: [B*N][64] u32.
__device__ float g_q[BB * NN * HH];
__device__ float g_k[BB * NN * HH];
__device__ float g_v[BB * NN * HH];
__device__ uint32_t g_mb[BB * NN * 64];

#define NCHUNK (BB * NN * 64 / 16)   // 262144 chunks of 16 words
#define NWARPS (512 * 3 * 8)         // 12288 packing warps

// pack two fp32 -> fp16x2 (lo = a, hi = b), saturating to finite
__device__ __forceinline__ uint32_t h2pack(float a, float b) {
    uint32_t r;
    asm("cvt.rn.satfinite.f16x2.f32 %0, %1, %2;" : "=r"(r) : "f"(b), "f"(a));
    return r;
}
__device__ __forceinline__ float tanha(float x) {
    float r;
    asm("tanh.approx.f32 %0, %1;" : "=f"(r) : "f"(x));
    return r;
}

// warp mma: D(16x8) += A(16x16,row,f16) * B(16x8,col,f16), fp32 accum
__device__ __forceinline__ void mma16n8k16h(float* c, const uint32_t* a,
                                            uint32_t b0, uint32_t b1) {
    asm volatile(
        "mma.sync.aligned.m16n8k16.row.col.f32.f16.f16.f32 "
        "{%0,%1,%2,%3}, {%4,%5,%6,%7}, {%8,%9}, {%0,%1,%2,%3};"
        : "+f"(c[0]), "+f"(c[1]), "+f"(c[2]), "+f"(c[3])
        : "r"(a[0]), "r"(a[1]), "r"(a[2]), "r"(a[3]), "r"(b0), "r"(b1));
}

__device__ __forceinline__ uint32_t smem_u32(const void* p) {
    uint32_t a;
    asm("{ .reg .u64 t; cvta.to.shared.u64 t, %1; cvt.u32.u64 %0, t; }"
        : "=r"(a) : "l"(p));
    return a;
}

#define CP_ASYNC16(dst, src)                                                \
    asm volatile("cp.async.cg.shared.global [%0], [%1], 16;" ::             \
                     "r"(dst), "l"(src) : "memory")
#define CP_COMMIT() asm volatile("cp.async.commit_group;" ::: "memory")
#define CP_WAIT0() asm volatile("cp.async.wait_group 0;" ::: "memory")
#define CP_WAIT1() asm volatile("cp.async.wait_group 1;" ::: "memory")

// ============================================================
// Kernel A: QKV projection via fp16 MMA with hi/lo error split,
// with the mask bit-pack INTERLEAVED into the MMA loop: each of the
// 24 kk-iterations issues one 16-word chunk's LDGs before its MMAs
// and ballots/stores after them, hiding the 512MB mask stream under
// compute (proj DRAM is otherwise ~idle).
//   y = tanh(x @ W + b);  y ~= xh@Wh + xh@Wl + xl@Wh  (fp32-faithful)
// smem (u32 words): Xh[128][68] | Xl[128][68] | Wh[128][68] | Wl[128][68]
// ============================================================
#define PW 68
#define PX_H 0
#define PX_L 8704
#define PW_H 17408
#define PW_L 26112
#define SMEM_PROJ (34816 * 4)

__global__ __launch_bounds__(256, 1) void proj_kernel(
    const float* __restrict__ x, const float* __restrict__ mask,
    const float* __restrict__ Wq, const float* __restrict__ bq,
    const float* __restrict__ Wk, const float* __restrict__ bk,
    const float* __restrict__ Wv, const float* __restrict__ bv) {
    extern __shared__ uint32_t ps[];
    const int tid = threadIdx.x;
    const int lane = tid & 31;
    const int w = tid >> 5;
    const int qp = lane >> 2;
    const int ql = lane & 3;
    const int row0 = blockIdx.x * 128;

    const float* W;
    const float* bias;
    float* outp;
    bool isV = false;
    if (blockIdx.y == 0)      { W = Wq; bias = bq; outp = g_q; }
    else if (blockIdx.y == 1) { W = Wk; bias = bk; outp = g_k; }
    else                      { W = Wv; bias = bv; outp = g_v; isV = true; }

    // packing warp id and first chunk
    uint32_t packc = (blockIdx.y * 512 + blockIdx.x) * 8 + w;

    // ---- load + split x tile (128 x 128 f32) ----
#pragma unroll
    for (int t = 0; t < 16; t++) {
        const int idx = tid + t * 256;
        const int row = idx >> 5, c = idx & 31;
        float4 v = *reinterpret_cast<const float4*>(
            x + (size_t)(row0 + row) * DD + 4 * c);
        float rx = __half2float(__float2half_rn(v.x));
        float ry = __half2float(__float2half_rn(v.y));
        float rz = __half2float(__float2half_rn(v.z));
        float rw = __half2float(__float2half_rn(v.w));
        uint2 uh, ul;
        uh.x = h2pack(v.x, v.y);
        uh.y = h2pack(v.z, v.w);
        ul.x = h2pack(v.x - rx, v.y - ry);
        ul.y = h2pack(v.z - rz, v.w - rw);
        *reinterpret_cast<uint2*>(ps + PX_H + row * PW + 2 * c) = uh;
        *reinterpret_cast<uint2*>(ps + PX_L + row * PW + 2 * c) = ul;
    }
    // ---- load + split W transposed: Wt[n][kp] = (W[2kp][n], W[2kp+1][n]) ----
#pragma unroll
    for (int t = 0; t < 32; t++) {
        const int idx = tid + t * 256;
        const int kp = idx >> 7, n = idx & 127;
        float a = __ldg(W + (size_t)(2 * kp) * HH + n);
        float b = __ldg(W + (size_t)(2 * kp + 1) * HH + n);
        float ra = __half2float(__float2half_rn(a));
        float rb = __half2float(__float2half_rn(b));
        ps[PW_H + n * PW + kp] = h2pack(a, b);
        ps[PW_L + n * PW + kp] = h2pack(a - ra, b - rb);
    }
    __syncthreads();

    // ---- 3-pass MMA with interleaved mask packing ----
    float oacc[16][4];
#pragma unroll
    for (int nb = 0; nb < 16; nb++)
#pragma unroll
        for (int c = 0; c < 4; c++) oacc[nb][c] = 0.0f;

    const int r0 = w * 16 + qp;
    const uint32_t* a0h = ps + PX_H + r0 * PW + ql;
    const uint32_t* a0l = ps + PX_L + r0 * PW + ql;

#pragma unroll 1
    for (int pass = 0; pass < 3; pass++) {
        const uint32_t* A0 = (pass == 2) ? a0l : a0h;
        const uint32_t* A1 = A0 + 8 * PW;
        const uint32_t* Wb = ps + ((pass == 1) ? PW_L : PW_H);
#pragma unroll
        for (int kk = 0; kk < 8; kk++) {
            // ---- issue pack-chunk loads (latency hidden by MMAs below) ----
            const bool act = (packc < NCHUNK);
            float mv[16];
            if (act) {
                const size_t base = (size_t)packc * 16;
#pragma unroll
                for (int u = 0; u < 16; u++)
                    mv[u] = __ldg(mask + (base + u) * 32 + lane);
            }

            uint32_t qa[4];
            qa[0] = A0[kk * 8];
            qa[1] = A1[kk * 8];
            qa[2] = A0[kk * 8 + 4];
            qa[3] = A1[kk * 8 + 4];
#pragma unroll
            for (int nb = 0; nb < 16; nb++) {
                const uint32_t* kb = Wb + (nb * 8 + qp) * PW + kk * 8 + ql;
                mma16n8k16h(oacc[nb], qa, kb[0], kb[4]);
            }

            // ---- finish pack chunk: ballots + store ----
            if (act) {
                uint32_t bits[16];
#pragma unroll
                for (int u = 0; u < 16; u++)
                    bits[u] = __ballot_sync(0xffffffffu, mv[u] != 0.0f);
                if (lane == 0) {
#pragma unroll
                    for (int u = 0; u < 16; u += 4) {
                        uint4 uu;
                        uu.x = bits[u];
                        uu.y = bits[u + 1];
                        uu.z = bits[u + 2];
                        uu.w = bits[u + 3];
                        *reinterpret_cast<uint4*>(g_mb + packc * 16 + u) = uu;
                    }
                }
            }
            packc += NWARPS;
        }
    }

    // ---- epilogue: bias + tanh.approx + pack + store ----
#pragma unroll
    for (int nb = 0; nb < 16; nb++) {
        const int n0 = nb * 8 + 2 * ql;
        float2 bb = __ldg(reinterpret_cast<const float2*>(bias + n0));
        float t0 = tanha(oacc[nb][0] + bb.x);
        float t1 = tanha(oacc[nb][1] + bb.y);
        float t2 = tanha(oacc[nb][2] + bb.x);
        float t3 = tanha(oacc[nb][3] + bb.y);
        if (!isV) {
            uint32_t* o2 = reinterpret_cast<uint32_t*>(outp);
            o2[(size_t)(row0 + r0) * 64 + nb * 4 + ql] = h2pack(t0, t1);
            o2[(size_t)(row0 + r0 + 8) * 64 + nb * 4 + ql] = h2pack(t2, t3);
        } else {
            float s0 = __shfl_xor_sync(0xffffffffu, t0, 4);
            float s1 = __shfl_xor_sync(0xffffffffu, t1, 4);
            float s2 = __shfl_xor_sync(0xffffffffu, t2, 4);
            float s3 = __shfl_xor_sync(0xffffffffu, t3, 4);
            uint32_t* v2 = reinterpret_cast<uint32_t*>(g_v);
            if (!(qp & 1)) {
                const size_t jp = (size_t)(row0 + w * 16 + qp) >> 1;
                uint2 u;
                u.x = h2pack(t0, s0);
                u.y = h2pack(t1, s1);
                *reinterpret_cast<uint2*>(v2 + jp * HH + nb * 8 + 2 * ql) = u;
            } else {
                const size_t jp = (size_t)(row0 + w * 16 + 8 + qp - 1) >> 1;
                uint2 u;
                u.x = h2pack(s2, t2);
                u.y = h2pack(s3, t3);
                *reinterpret_cast<uint2*>(v2 + jp * HH + nb * 8 + 2 * ql) = u;
            }
        }
    }
}

// ============================================================
// Kernel B: flash attention v13 (unchanged — 299us measured).
//  - 64-j stages (32 stages), triple-buffered K/V, ONE sync/stage
//  - Q fragments persistent in registers; BIT mask (one u64 LDG per
//    row-pair per stage) -> no mask cp.async, no mask smem
// smem (words): Kh 3x[64][68] | Vt 3x[32][136]  = 102 KB
// ============================================================
#define QLDH 68
#define KSTRIDE (64 * QLDH)
#define VT_OFF (3 * KSTRIDE)
#define VSTRIDE (32 * 136)
#define SMEM_ATT ((VT_OFF + 3 * VSTRIDE) * 4)

__device__ __forceinline__ void attn_stage_copy(uint32_t smb, int s,
                                                const uint32_t* kg2,
                                                const uint32_t* vg2, int tid) {
    const int buf = s % 3;
    const uint32_t kdst = smb + (uint32_t)(buf * KSTRIDE) * 4;
    const uint32_t vdst = smb + (uint32_t)(VT_OFF + buf * VSTRIDE) * 4;
    const uint32_t* kn = kg2 + (size_t)(s * 64) * 64;
    const uint32_t* vn = vg2 + (size_t)(s * 32) * HH;
#pragma unroll
    for (int t = 0; t < 4; t++) {
        const int idx = tid + t * 256;       // 0..1023
        const int krow = idx >> 4, kc = idx & 15;
        CP_ASYNC16(kdst + (uint32_t)(krow * QLDH + kc * 4) * 4,
                   kn + (size_t)krow * 64 + kc * 4);
        const int vrow = idx >> 5, vc = idx & 31;
        CP_ASYNC16(vdst + (uint32_t)(vrow * 136 + vc * 4) * 4,
                   vn + (size_t)vrow * HH + vc * 4);
    }
}

__global__ __launch_bounds__(256, 2) void attn_mma(float* __restrict__ out) {
    extern __shared__ uint32_t smw[];
    const uint32_t smb = smem_u32(smw);

    const int tid = threadIdx.x;
    const int lane = tid & 31;
    const int w = tid >> 5;
    const int b = blockIdx.x >> 4;
    const int i0 = (blockIdx.x & 15) << 7;
    const int qp = lane >> 2;
    const int ql = lane & 3;
    const int r0 = w * 16 + qp;

    const uint32_t* qg2 =
        reinterpret_cast<const uint32_t*>(g_q) + ((size_t)(b * NN) + i0) * 64;
    const uint32_t* kg2 =
        reinterpret_cast<const uint32_t*>(g_k) + (size_t)(b * NN) * 64;
    const uint32_t* vg2 =
        reinterpret_cast<const uint32_t*>(g_v) + (size_t)b * 1024 * HH;
    const uint32_t* mb0 = g_mb + ((size_t)(b * NN) + i0 + r0) * 64;
    const uint32_t* mb1 = mb0 + (size_t)8 * 64;

    // ---- prologue: stage0, stage1 copies in flight ----
    attn_stage_copy(smb, 0, kg2, vg2, tid);
    CP_COMMIT();
    attn_stage_copy(smb, 1, kg2, vg2, tid);
    CP_COMMIT();

    // ---- persistent Q fragments in registers (fp16-packed) ----
    uint32_t qa_all[8][4];
    {
        const uint32_t* q0 = qg2 + (size_t)r0 * 64 + ql;
        const uint32_t* q1 = qg2 + (size_t)(r0 + 8) * 64 + ql;
#pragma unroll
        for (int kk = 0; kk < 8; kk++) {
            qa_all[kk][0] = __ldg(q0 + kk * 8);
            qa_all[kk][1] = __ldg(q1 + kk * 8);
            qa_all[kk][2] = __ldg(q0 + kk * 8 + 4);
            qa_all[kk][3] = __ldg(q1 + kk * 8 + 4);
        }
    }

    float oa[16][4];
#pragma unroll
    for (int h = 0; h < 16; h++)
#pragma unroll
        for (int c = 0; c < 4; c++) oa[h][c] = 0.0f;
    float ls0 = 0.0f, ls1 = 0.0f;

#pragma unroll 1
    for (int jt = 0; jt < 32; jt++) {
        if (jt < 31) { CP_WAIT1(); } else { CP_WAIT0(); }
        __syncthreads();   // stage jt resident; all warps done with jt-1

        if (jt < 30) {
            attn_stage_copy(smb, jt + 2, kg2, vg2, tid);
            CP_COMMIT();
        }

        const uint32_t* Kh = smw + (jt % 3) * KSTRIDE;
        const uint32_t* sVt = smw + VT_OFF + (jt % 3) * VSTRIDE;

        // ---- bit mask for this 64-j stage: one u64 per row ----
        const unsigned long long mw0 = __ldg(
            reinterpret_cast<const unsigned long long*>(mb0 + 2 * jt));
        const unsigned long long mw1 = __ldg(
            reinterpret_cast<const unsigned long long*>(mb1 + 2 * jt));

#pragma unroll
        for (int hf = 0; hf < 2; hf++) {
            const uint32_t w0 = (uint32_t)(mw0 >> (hf * 32));
            const uint32_t w1 = (uint32_t)(mw1 >> (hf * 32));

            // ---- S = Q K^T over this half's 32 j ----
            float sf[4][4];
#pragma unroll
            for (int nb = 0; nb < 4; nb++)
#pragma unroll
                for (int c = 0; c < 4; c++) sf[nb][c] = 0.0f;

#pragma unroll
            for (int kk = 0; kk < 8; kk++) {
#pragma unroll
                for (int nb = 0; nb < 4; nb++) {
                    const uint32_t* kb =
                        Kh + (hf * 32 + nb * 8 + qp) * QLDH + kk * 8 + ql;
                    mma16n8k16h(sf[nb], qa_all[kk], kb[0], kb[4]);
                }
            }

            // ---- per nb-pair: bit test + exp(s-10) + fp16 pack + PV ----
#pragma unroll
            for (int m = 0; m < 2; m++) {
                const int nE = 2 * m, nO = 2 * m + 1;
                const int bE = nE * 8 + 2 * ql;
                const int bO = nO * 8 + 2 * ql;
                float pE0 = ((w0 >> bE) & 1u) ? __expf(sf[nE][0] - 10.0f) : 0.0f;
                float pE1 = ((w0 >> (bE + 1)) & 1u) ? __expf(sf[nE][1] - 10.0f) : 0.0f;
                float pE2 = ((w1 >> bE) & 1u) ? __expf(sf[nE][2] - 10.0f) : 0.0f;
                float pE3 = ((w1 >> (bE + 1)) & 1u) ? __expf(sf[nE][3] - 10.0f) : 0.0f;
                float pO0 = ((w0 >> bO) & 1u) ? __expf(sf[nO][0] - 10.0f) : 0.0f;
                float pO1 = ((w0 >> (bO + 1)) & 1u) ? __expf(sf[nO][1] - 10.0f) : 0.0f;
                float pO2 = ((w1 >> bO) & 1u) ? __expf(sf[nO][2] - 10.0f) : 0.0f;
                float pO3 = ((w1 >> (bO + 1)) & 1u) ? __expf(sf[nO][3] - 10.0f) : 0.0f;
                ls0 += (pE0 + pE1) + (pO0 + pO1);
                ls1 += (pE2 + pE3) + (pO2 + pO3);
                uint32_t pa[4];
                pa[0] = h2pack(pE0, pE1);
                pa[1] = h2pack(pE2, pE3);
                pa[2] = h2pack(pO0, pO1);
                pa[3] = h2pack(pO3 == pO3 ? pO2 : pO2, pO3);

                const uint32_t* vb0 = sVt + (hf * 16 + m * 8 + ql) * 136 + qp;
                const uint32_t* vb1 = vb0 + 4 * 136;
#pragma unroll
                for (int h = 0; h < 16; h++) {
                    mma16n8k16h(oa[h], pa, vb0[h * 8], vb1[h * 8]);
                }
            }
        }
    }

    // ---- epilogue: quad reduction, normalize, store ----
    ls0 += __shfl_xor_sync(0xffffffffu, ls0, 1);
    ls0 += __shfl_xor_sync(0xffffffffu, ls0, 2);
    ls1 += __shfl_xor_sync(0xffffffffu, ls1, 1);
    ls1 += __shfl_xor_sync(0xffffffffu, ls1, 2);
    const float inv0 = 1.0f / ls0;
    const float inv1 = 1.0f / ls1;
    float* orow0 = out + ((size_t)(b * NN) + i0 + r0) * HH + 2 * ql;
    float* orow1 = orow0 + (size_t)8 * HH;
#pragma unroll
    for (int h = 0; h < 16; h++) {
        float2 v0, v1;
        v0.x = oa[h][0] * inv0; v0.y = oa[h][1] * inv0;
        v1.x = oa[h][2] * inv1; v1.y = oa[h][3] * inv1;
        *reinterpret_cast<float2*>(orow0 + h * 8) = v0;
        *reinterpret_cast<float2*>(orow1 + h * 8) = v1;
    }
}

extern "C" void kernel_launch(void* const* d_in, const int* in_sizes, int n_in,
                              void* d_out, int out_size) {
    const float* x    = (const float*)d_in[0];
    const float* mask = (const float*)d_in[1];
    const float* Wv   = (const float*)d_in[2];
    const float* bv   = (const float*)d_in[3];
    const float* Wk   = (const float*)d_in[4];
    const float* bk   = (const float*)d_in[5];
    const float* Wq   = (const float*)d_in[6];
    const float* bq   = (const float*)d_in[7];
    float* out = (float*)d_out;

    cudaFuncSetAttribute(proj_kernel, cudaFuncAttributeMaxDynamicSharedMemorySize,
                         SMEM_PROJ);
    cudaFuncSetAttribute(attn_mma, cudaFuncAttributeMaxDynamicSharedMemorySize,
                         SMEM_ATT);

    proj_kernel<<<dim3(512, 3, 1), 256, SMEM_PROJ>>>(x, mask, Wq, bq, Wk, bk,
                                                     Wv, bv);
    attn_mma<<<512, 256, SMEM_ATT>>>(out);
}